// round 12
// baseline (speedup 1.0000x reference)
#include <cuda_runtime.h>
#include <cuda_fp16.h>
#include <cstdint>

#define NROWS 8192
#define DDIM  256
#define KN    10
#define NTB   64                   // 128-col blocks per row

// ---------------- scratch (static device globals; no allocation) ----------------
__device__ __half    g_Bh[(size_t)NROWS * DDIM];     // fp16(feats/||feats||)
__device__ float     g_invn[NROWS];                  // 1/||feats||
__device__ __half    g_simh[(size_t)NROWS * NROWS];  // fp16 cos (symmetric, 128 MB)
__device__ uint32_t  g_bmax[(size_t)NROWS * NTB];    // per-128-col block maxima (monotone keys of STORED halves)
__device__ int       g_topk[NROWS * KN];
__device__ int       g_dv[NROWS];

__device__ __forceinline__ uint32_t smem_u32(const void* p) {
    uint32_t a;
    asm("{ .reg .u64 t; cvta.to.shared.u64 t, %1; cvt.u32.u64 %0, t; }" : "=r"(a) : "l"(p));
    return a;
}
// monotone float->uint key (total order incl. negatives)
__device__ __forceinline__ uint32_t fkey(float f) {
    uint32_t u = __float_as_uint(f);
    return (u & 0x80000000u) ? ~u : (u | 0x80000000u);
}
__device__ __forceinline__ float fkeyinv(uint32_t k) {
    return (k & 0x80000000u) ? __uint_as_float(k ^ 0x80000000u) : __uint_as_float(~k);
}

// ---------------- kernel 1: prep — norms, fp16 normalized rows; zero dv ----------------
__global__ __launch_bounds__(256) void k_prep(const float* __restrict__ feats) {
    int warp = (blockIdx.x * blockDim.x + threadIdx.x) >> 5;
    int lane = threadIdx.x & 31;
    if (warp < NROWS) {
        const float* x = feats + (size_t)warp * DDIM;
        float s = 0.f;
        #pragma unroll
        for (int k = lane; k < DDIM; k += 32) { float v = x[k]; s += v * v; }
        #pragma unroll
        for (int off = 16; off; off >>= 1) s += __shfl_xor_sync(0xffffffffu, s, off);
        float inv = 1.0f / sqrtf(s);
        if (lane == 0) g_invn[warp] = inv;
        __half* br = g_Bh + (size_t)warp * DDIM;
        #pragma unroll
        for (int k = lane; k < DDIM; k += 32)
            br[k] = __float2half(x[k] * inv);
    }
    int gt = blockIdx.x * blockDim.x + threadIdx.x;
    if (gt < NROWS) g_dv[gt] = 0;
}

// ---------------- kernel 2: symmetric HMMA GEMM (upper-triangle tiles + mirror),
//                  half store, block-max epilogue, folded output zeroing ----------------
#define BM 128
#define BK 32
#define STAGES 3
#define KITER (DDIM / BK)          // 8
#define SSTRIDE 40
#define STAGE_HALF (BM * SSTRIDE)
#define STAGE_BYTES (2 * STAGE_HALF * 2)
#define GEMM_SMEM (STAGES * STAGE_BYTES)   // 61440
#define NTRI (NTB * (NTB + 1) / 2)         // 2080
// epilogue smem offsets (bytes, within the same dynamic smem)
#define EP_STAGE   0                        // 128 x 136 halves = 34816
#define EP_COLMAX  34816                    // 128 u32 = 512
#define EP_SMAX    35840                    // 256 u32 = 1024

__device__ __forceinline__ void ldsm_x4(uint32_t* r, uint32_t addr) {
    asm volatile("ldmatrix.sync.aligned.m8n8.x4.shared.b16 {%0,%1,%2,%3}, [%4];"
                 : "=r"(r[0]), "=r"(r[1]), "=r"(r[2]), "=r"(r[3]) : "r"(addr));
}
__device__ __forceinline__ void mma16816(float* c, const uint32_t* a, uint32_t b0, uint32_t b1) {
    asm volatile("mma.sync.aligned.m16n8k16.row.col.f32.f16.f16.f32 "
                 "{%0,%1,%2,%3}, {%4,%5,%6,%7}, {%8,%9}, {%0,%1,%2,%3};"
                 : "+f"(c[0]), "+f"(c[1]), "+f"(c[2]), "+f"(c[3])
                 : "r"(a[0]), "r"(a[1]), "r"(a[2]), "r"(a[3]), "r"(b0), "r"(b1));
}

__global__ __launch_bounds__(256, 2) void k_gemm(float4* __restrict__ out4) {
    extern __shared__ __half smem[];
    uint32_t sbase = smem_u32(smem);
    int tid = threadIdx.x, lane = tid & 31, wid = tid >> 5;

    // upper-triangle tile decode
    int t = blockIdx.x, by = 0;
    #pragma unroll 1
    for (int r = 0; r < NTB; r++) { int len = NTB - r; if (t < len) { by = r; break; } t -= len; }
    int bx = by + t;
    int bm = by * BM, bn = bx * BM;
    bool diag = (bx == by);

    // folded output zeroing (grid-stride over 16.7M float4)
    {
        float4 z = make_float4(0.f, 0.f, 0.f, 0.f);
        size_t n4 = (size_t)NROWS * NROWS / 4;
        size_t stride = (size_t)gridDim.x * 256;
        for (size_t i = (size_t)blockIdx.x * 256 + tid; i < n4; i += stride) out4[i] = z;
    }

    int wm0 = (wid >> 1) * 32;
    int wn0 = (wid & 1) * 64;
    int r0 = tid >> 2, s0 = tid & 3;
    int r1 = (tid + 256) >> 2, s1 = (tid + 256) & 3;
    const __half* gA = g_Bh + (size_t)bm * DDIM;
    const __half* gB = g_Bh + (size_t)bn * DDIM;

    float acc[2][8][4];
    #pragma unroll
    for (int mt = 0; mt < 2; mt++)
        #pragma unroll
        for (int nt = 0; nt < 8; nt++)
            #pragma unroll
            for (int i = 0; i < 4; i++) acc[mt][nt][i] = 0.f;

    #pragma unroll
    for (int s = 0; s < STAGES - 1; s++) {
        int k0 = s * BK;
        uint32_t sa = sbase + s * STAGE_BYTES;
        uint32_t sbm = sa + STAGE_HALF * 2;
        asm volatile("cp.async.cg.shared.global [%0], [%1], 16;" ::
                     "r"(sa + (r0 * SSTRIDE + s0 * 8) * 2), "l"(gA + (size_t)r0 * DDIM + k0 + s0 * 8));
        asm volatile("cp.async.cg.shared.global [%0], [%1], 16;" ::
                     "r"(sa + (r1 * SSTRIDE + s1 * 8) * 2), "l"(gA + (size_t)r1 * DDIM + k0 + s1 * 8));
        asm volatile("cp.async.cg.shared.global [%0], [%1], 16;" ::
                     "r"(sbm + (r0 * SSTRIDE + s0 * 8) * 2), "l"(gB + (size_t)r0 * DDIM + k0 + s0 * 8));
        asm volatile("cp.async.cg.shared.global [%0], [%1], 16;" ::
                     "r"(sbm + (r1 * SSTRIDE + s1 * 8) * 2), "l"(gB + (size_t)r1 * DDIM + k0 + s1 * 8));
        asm volatile("cp.async.commit_group;");
    }

    for (int i = 0; i < KITER; i++) {
        asm volatile("cp.async.wait_group %0;" :: "n"(STAGES - 2));
        __syncthreads();
        int st = i % STAGES;
        uint32_t As = sbase + st * STAGE_BYTES;
        uint32_t Bs = As + STAGE_HALF * 2;

        #pragma unroll
        for (int ks = 0; ks < 2; ks++) {
            uint32_t a[2][4];
            #pragma unroll
            for (int mt = 0; mt < 2; mt++)
                ldsm_x4(a[mt], As + ((wm0 + mt * 16 + (lane & 15)) * SSTRIDE + ks * 16 + (lane >> 4) * 8) * 2);
            #pragma unroll
            for (int ng = 0; ng < 4; ng++) {
                uint32_t b[4];
                ldsm_x4(b, Bs + ((wn0 + ng * 16 + (lane & 15)) * SSTRIDE + ks * 16 + (lane >> 4) * 8) * 2);
                #pragma unroll
                for (int mt = 0; mt < 2; mt++) {
                    mma16816(acc[mt][ng * 2 + 0], a[mt], b[0], b[2]);
                    mma16816(acc[mt][ng * 2 + 1], a[mt], b[1], b[3]);
                }
            }
        }

        int pf = i + STAGES - 1;
        if (pf < KITER) {
            int k0 = pf * BK;
            uint32_t sa = sbase + (pf % STAGES) * STAGE_BYTES;
            uint32_t sbm = sa + STAGE_HALF * 2;
            asm volatile("cp.async.cg.shared.global [%0], [%1], 16;" ::
                         "r"(sa + (r0 * SSTRIDE + s0 * 8) * 2), "l"(gA + (size_t)r0 * DDIM + k0 + s0 * 8));
            asm volatile("cp.async.cg.shared.global [%0], [%1], 16;" ::
                         "r"(sa + (r1 * SSTRIDE + s1 * 8) * 2), "l"(gA + (size_t)r1 * DDIM + k0 + s1 * 8));
            asm volatile("cp.async.cg.shared.global [%0], [%1], 16;" ::
                         "r"(sbm + (r0 * SSTRIDE + s0 * 8) * 2), "l"(gB + (size_t)r0 * DDIM + k0 + s0 * 8));
            asm volatile("cp.async.cg.shared.global [%0], [%1], 16;" ::
                         "r"(sbm + (r1 * SSTRIDE + s1 * 8) * 2), "l"(gB + (size_t)r1 * DDIM + k0 + s1 * 8));
        }
        asm volatile("cp.async.commit_group;");
        __syncthreads();
    }

    asm volatile("cp.async.wait_group 0;" ::);
    __syncthreads();

    char* smc = (char*)smem;
    uint32_t* smax = (uint32_t*)(smc + EP_SMAX);      // [128][2]
    if (tid < 256) smax[tid] = 0;
    __syncthreads();

    const float NEG_INF = __int_as_float(0xff800000);
    int gid = lane >> 2, tig = lane & 3;

    // ---- direct store (rows bm.., cols bn..) + row maxima of STORED halves ----
    #pragma unroll
    for (int mt = 0; mt < 2; mt++) {
        int row = bm + wm0 + mt * 16 + gid;
        float mx0 = NEG_INF, mx1 = NEG_INF;
        #pragma unroll
        for (int nt = 0; nt < 8; nt++) {
            int col = bn + wn0 + nt * 8 + 2 * tig;
            __half2 h0 = __floats2half2_rn(acc[mt][nt][0], acc[mt][nt][1]);
            __half2 h1 = __floats2half2_rn(acc[mt][nt][2], acc[mt][nt][3]);
            *(__half2*)(g_simh + (size_t)row * NROWS + col) = h0;
            *(__half2*)(g_simh + (size_t)(row + 8) * NROWS + col) = h1;
            float2 f0 = __half22float2(h0), f1 = __half22float2(h1);
            mx0 = fmaxf(mx0, fmaxf(f0.x, f0.y));
            mx1 = fmaxf(mx1, fmaxf(f1.x, f1.y));
        }
        mx0 = fmaxf(mx0, __shfl_xor_sync(0xffffffffu, mx0, 1));
        mx0 = fmaxf(mx0, __shfl_xor_sync(0xffffffffu, mx0, 2));
        mx1 = fmaxf(mx1, __shfl_xor_sync(0xffffffffu, mx1, 1));
        mx1 = fmaxf(mx1, __shfl_xor_sync(0xffffffffu, mx1, 2));
        if (tig == 0) {
            smax[(wm0 + mt * 16 + gid) * 2 + (wid & 1)] = fkey(mx0);
            smax[(wm0 + mt * 16 + 8 + gid) * 2 + (wid & 1)] = fkey(mx1);
        }
    }
    __syncthreads();
    if (tid < 128) {
        uint32_t k = max(smax[tid * 2], smax[tid * 2 + 1]);
        g_bmax[(size_t)(bm + tid) * NTB + bx] = k;
    }

    // ---- mirror (off-diagonal): transpose via smem, store rows bn.., cols bm.. ----
    if (!diag) {
        __half*   stage  = (__half*)(smc + EP_STAGE);     // [col][row] 128 x 136
        uint32_t* colmax = (uint32_t*)(smc + EP_COLMAX);  // [128]
        if (tid < 128) colmax[tid] = 0;
        __syncthreads();

        #pragma unroll
        for (int nt = 0; nt < 8; nt++) {
            #pragma unroll
            for (int e = 0; e < 2; e++) {
                int col = wn0 + nt * 8 + 2 * tig + e;       // 0..127 (tile col)
                float cm = NEG_INF;
                #pragma unroll
                for (int mt = 0; mt < 2; mt++) {
                    #pragma unroll
                    for (int h = 0; h < 2; h++) {
                        float v = acc[mt][nt][h * 2 + e];
                        __half hv = __float2half_rn(v);
                        int rowi = wm0 + mt * 16 + h * 8 + gid; // 0..127 (tile row)
                        stage[col * 136 + rowi] = hv;
                        cm = fmaxf(cm, __half2float(hv));
                    }
                }
                cm = fmaxf(cm, __shfl_xor_sync(0xffffffffu, cm, 4));
                cm = fmaxf(cm, __shfl_xor_sync(0xffffffffu, cm, 8));
                cm = fmaxf(cm, __shfl_xor_sync(0xffffffffu, cm, 16));
                if (gid == 0) atomicMax(&colmax[col], fkey(cm));
            }
        }
        __syncthreads();

        #pragma unroll
        for (int i = 0; i < 8; i++) {
            int c = tid + i * 256;
            int trow = c >> 4, tc = c & 15;
            uint4 v = *(uint4*)(stage + trow * 136 + tc * 8);
            *(uint4*)(g_simh + (size_t)(bn + trow) * NROWS + bm + tc * 8) = v;
        }
        if (tid < 128)
            g_bmax[(size_t)(bn + tid) * NTB + by] = colmax[tid];
    }
}

// ---------------- kernel 3: per-row block (128 thr): fused theta + masked gather +
//                  WARP-per-candidate coalesced exact rescore + exact top-10 ----------------
#define TCAP 512
__device__ __forceinline__ void topk_ins(float v, int j, float* bv, int* bi) {
    if (v > bv[KN - 1] || (v == bv[KN - 1] && j < bi[KN - 1])) {
        float cv = v; int ci = j;
        #pragma unroll
        for (int t = 0; t < KN; t++) {
            bool better = (cv > bv[t]) || (cv == bv[t] && ci < bi[t]);
            if (better) {
                float tv = bv[t]; int ti = bi[t];
                bv[t] = cv; bi[t] = ci;
                cv = tv; ci = ti;
            }
        }
    }
}

__global__ __launch_bounds__(128) void k_topk(const float* __restrict__ feats) {
    __shared__ int   sli[TCAP];
    __shared__ float slv[TCAP];
    __shared__ int   scnt;
    __shared__ float s_theta;
    __shared__ unsigned long long s_mask;
    int tid = threadIdx.x, w = tid >> 5, lane = tid & 31;
    int row = blockIdx.x;
    const float NEG_INF = __int_as_float(0xff800000);

    // warp 0: theta = 20th largest of 64 block maxima; mask = blocks with bmax >= theta
    if (w == 0) {
        const uint32_t* bk = g_bmax + (size_t)row * NTB;
        uint32_t v0 = bk[lane], v1 = bk[lane + 32];
        uint32_t v0o = v0, v1o = v1, M = 0;
        #pragma unroll 1
        for (int r = 0; r < 20; r++) {
            uint32_t lm = max(v0, v1);
            M = lm;
            #pragma unroll
            for (int off = 16; off; off >>= 1) M = max(M, __shfl_xor_sync(0xffffffffu, M, off));
            unsigned b = __ballot_sync(0xffffffffu, lm == M);
            if (lane == __ffs(b) - 1) { if (v0 == M) v0 = 0; else v1 = 0; }
        }
        unsigned m0 = __ballot_sync(0xffffffffu, v0o >= M);
        unsigned m1 = __ballot_sync(0xffffffffu, v1o >= M);
        if (lane == 0) {
            s_theta = fkeyinv(M);
            s_mask = (unsigned long long)m0 | ((unsigned long long)m1 << 32);
            scnt = 0;
        }
    }
    __syncthreads();
    float theta = s_theta;

    // gather: 4 warps split flagged blocks round-robin (coalesced uint2 = 4 halves/lane)
    {
        unsigned long long m = s_mask;
        int idx = 0;
        while (m) {
            int b = __ffsll(m) - 1; m &= m - 1;
            if ((idx & 3) == w) {
                uint2 q = *(const uint2*)(g_simh + (size_t)row * NROWS + b * 128 + lane * 4);
                __half2 p0 = *(__half2*)&q.x, p1 = *(__half2*)&q.y;
                float2 f0 = __half22float2(p0), f1 = __half22float2(p1);
                float mx = fmaxf(fmaxf(f0.x, f0.y), fmaxf(f1.x, f1.y));
                if (mx >= theta) {
                    int jb = b * 128 + lane * 4;
                    if (f0.x >= theta) { int p = atomicAdd(&scnt, 1); if (p < TCAP) sli[p] = jb + 0; }
                    if (f0.y >= theta) { int p = atomicAdd(&scnt, 1); if (p < TCAP) sli[p] = jb + 1; }
                    if (f1.x >= theta) { int p = atomicAdd(&scnt, 1); if (p < TCAP) sli[p] = jb + 2; }
                    if (f1.y >= theta) { int p = atomicAdd(&scnt, 1); if (p < TCAP) sli[p] = jb + 3; }
                }
            }
            idx++;
        }
    }
    __syncthreads();
    int cnt = scnt;

    const float4* fr = (const float4*)(feats + (size_t)row * DDIM);
    if (cnt <= TCAP) {
        // exact fp32 rescore, WARP per candidate: lane l covers float4s {2l, 2l+1}
        // (coalesced: 8 cache lines per candidate instead of 32 per load)
        float4 a0 = fr[2 * lane], a1 = fr[2 * lane + 1];
        for (int i = w; i < cnt; i += 4) {
            int j = sli[i];
            const float4* fj = (const float4*)(feats + (size_t)j * DDIM);
            float4 b0 = fj[2 * lane], b1 = fj[2 * lane + 1];
            float s = a0.x * b0.x + a0.y * b0.y + a0.z * b0.z + a0.w * b0.w
                    + a1.x * b1.x + a1.y * b1.y + a1.z * b1.z + a1.w * b1.w;
            #pragma unroll
            for (int off = 16; off; off >>= 1) s += __shfl_xor_sync(0xffffffffu, s, off);
            if (lane == 0) slv[i] = s * g_invn[j];
        }
        __syncthreads();
        if (w == 0) {
            float bv[KN]; int bi[KN];
            #pragma unroll
            for (int t = 0; t < KN; t++) { bv[t] = NEG_INF; bi[t] = 0x7fffffff; }
            for (int i = lane; i < cnt; i += 32) topk_ins(slv[i], sli[i], bv, bi);
            #pragma unroll 1
            for (int r = 0; r < KN; r++) {
                float mv = bv[0]; int mi = bi[0];
                #pragma unroll
                for (int off = 16; off; off >>= 1) {
                    float ov = __shfl_xor_sync(0xffffffffu, mv, off);
                    int   oi = __shfl_xor_sync(0xffffffffu, mi, off);
                    if (ov > mv || (ov == mv && oi < mi)) { mv = ov; mi = oi; }
                }
                if (mi == bi[0]) {
                    #pragma unroll
                    for (int t = 0; t < KN - 1; t++) { bv[t] = bv[t + 1]; bi[t] = bi[t + 1]; }
                    bv[KN - 1] = NEG_INF; bi[KN - 1] = 0x7fffffff;
                }
                if (lane == 0) {
                    g_topk[row * KN + r] = mi;
                    atomicAdd(&g_dv[mi], 1);
                }
            }
        }
    } else if (w == 0) {
        // exact fallback (never expected): full warp-per-candidate rescore of the row
        float4 a0 = fr[2 * lane], a1 = fr[2 * lane + 1];
        float bv[KN]; int bi[KN];
        #pragma unroll
        for (int t = 0; t < KN; t++) { bv[t] = NEG_INF; bi[t] = 0x7fffffff; }
        for (int j = 0; j < NROWS; j++) {
            const float4* fj = (const float4*)(feats + (size_t)j * DDIM);
            float4 b0 = fj[2 * lane], b1 = fj[2 * lane + 1];
            float s = a0.x * b0.x + a0.y * b0.y + a0.z * b0.z + a0.w * b0.w
                    + a1.x * b1.x + a1.y * b1.y + a1.z * b1.z + a1.w * b1.w;
            #pragma unroll
            for (int off = 16; off; off >>= 1) s += __shfl_xor_sync(0xffffffffu, s, off);
            topk_ins(s * g_invn[j], j, bv, bi);   // same value in all lanes
        }
        #pragma unroll 1
        for (int r = 0; r < KN; r++) {
            if (lane == 0) {
                g_topk[row * KN + r] = bi[0];
                atomicAdd(&g_dv[bi[0]], 1);
            }
            #pragma unroll
            for (int t = 0; t < KN - 1; t++) { bv[t] = bv[t + 1]; bi[t] = bi[t + 1]; }
        }
    }
}

// ---------------- kernel 4: scatter 10x10 outer products (invdv fused) ----------------
__global__ __launch_bounds__(128) void k_scatter(float* __restrict__ out) {
    __shared__ int   sidx[KN];
    __shared__ float sw[KN];
    int e = blockIdx.x;
    int t = threadIdx.x;
    if (t < KN) {
        int a = g_topk[e * KN + t];
        sidx[t] = a;
        int d = g_dv[a];
        sw[t] = d > 0 ? 1.0f / sqrtf((float)d) : 0.0f;
    }
    __syncthreads();
    if (t < KN * KN) {
        int a = sidx[t / KN];
        int b = sidx[t % KN];
        float val = (0.1f * sw[t / KN]) * sw[t % KN];
        atomicAdd(&out[(size_t)a * NROWS + b], val);
    }
}

// ---------------- launch ----------------
extern "C" void kernel_launch(void* const* d_in, const int* in_sizes, int n_in,
                              void* d_out, int out_size) {
    const float* feats = (const float*)d_in[0];
    float* out = (float*)d_out;

    k_prep<<<(NROWS * 32) / 256, 256>>>(feats);

    cudaFuncSetAttribute(k_gemm, cudaFuncAttributeMaxDynamicSharedMemorySize, GEMM_SMEM);
    k_gemm<<<NTRI, 256, GEMM_SMEM>>>((float4*)out);

    k_topk<<<NROWS, 128>>>(feats);
    k_scatter<<<NROWS, 128>>>(out);
}

// round 13
// speedup vs baseline: 1.5299x; 1.5299x over previous
#include <cuda_runtime.h>
#include <cuda_fp16.h>
#include <cstdint>

#define NROWS 8192
#define DDIM  256
#define KN    10
#define NTB   64                   // 128-col blocks per row

// ---------------- scratch (static device globals; no allocation) ----------------
__device__ __half    g_Bh[(size_t)NROWS * DDIM];     // fp16(feats/||feats||)
__device__ float     g_invn[NROWS];                  // 1/||feats||
__device__ __half    g_simh[(size_t)NROWS * NROWS];  // fp16 cos (symmetric, 128 MB)
__device__ uint32_t  g_bmax[(size_t)NROWS * NTB];    // per-128-col block maxima (monotone keys of STORED halves)
__device__ float     g_theta[NROWS];
__device__ unsigned long long g_bmask[NROWS];        // blocks with bmax >= theta
__device__ int       g_topk[NROWS * KN];
__device__ int       g_dv[NROWS];
__device__ float     g_invdv[NROWS];

__device__ __forceinline__ uint32_t smem_u32(const void* p) {
    uint32_t a;
    asm("{ .reg .u64 t; cvta.to.shared.u64 t, %1; cvt.u32.u64 %0, t; }" : "=r"(a) : "l"(p));
    return a;
}
// monotone float->uint key (total order incl. negatives)
__device__ __forceinline__ uint32_t fkey(float f) {
    uint32_t u = __float_as_uint(f);
    return (u & 0x80000000u) ? ~u : (u | 0x80000000u);
}
__device__ __forceinline__ float fkeyinv(uint32_t k) {
    return (k & 0x80000000u) ? __uint_as_float(k ^ 0x80000000u) : __uint_as_float(~k);
}

// ---------------- kernel 1: prep — norms, fp16 normalized rows; zero dv ----------------
__global__ __launch_bounds__(256) void k_prep(const float* __restrict__ feats) {
    int warp = (blockIdx.x * blockDim.x + threadIdx.x) >> 5;
    int lane = threadIdx.x & 31;
    if (warp < NROWS) {
        const float* x = feats + (size_t)warp * DDIM;
        float s = 0.f;
        #pragma unroll
        for (int k = lane; k < DDIM; k += 32) { float v = x[k]; s += v * v; }
        #pragma unroll
        for (int off = 16; off; off >>= 1) s += __shfl_xor_sync(0xffffffffu, s, off);
        float inv = 1.0f / sqrtf(s);
        if (lane == 0) g_invn[warp] = inv;
        __half* br = g_Bh + (size_t)warp * DDIM;
        #pragma unroll
        for (int k = lane; k < DDIM; k += 32)
            br[k] = __float2half(x[k] * inv);
    }
    int gt = blockIdx.x * blockDim.x + threadIdx.x;
    if (gt < NROWS) g_dv[gt] = 0;
}

// ---------------- kernel 2: symmetric HMMA GEMM (upper-triangle tiles + mirror),
//                  half store, block-max epilogue, folded output zeroing ----------------
#define BM 128
#define BK 32
#define STAGES 3
#define KITER (DDIM / BK)          // 8
#define SSTRIDE 40
#define STAGE_HALF (BM * SSTRIDE)
#define STAGE_BYTES (2 * STAGE_HALF * 2)
#define GEMM_SMEM (STAGES * STAGE_BYTES)   // 61440
#define NTRI (NTB * (NTB + 1) / 2)         // 2080
// epilogue smem offsets (bytes, within the same dynamic smem)
#define EP_STAGE   0                        // 128 x 136 halves = 34816
#define EP_COLMAX  34816                    // 128 u32 = 512
#define EP_SMAX    35840                    // 256 u32 = 1024

__device__ __forceinline__ void ldsm_x4(uint32_t* r, uint32_t addr) {
    asm volatile("ldmatrix.sync.aligned.m8n8.x4.shared.b16 {%0,%1,%2,%3}, [%4];"
                 : "=r"(r[0]), "=r"(r[1]), "=r"(r[2]), "=r"(r[3]) : "r"(addr));
}
__device__ __forceinline__ void mma16816(float* c, const uint32_t* a, uint32_t b0, uint32_t b1) {
    asm volatile("mma.sync.aligned.m16n8k16.row.col.f32.f16.f16.f32 "
                 "{%0,%1,%2,%3}, {%4,%5,%6,%7}, {%8,%9}, {%0,%1,%2,%3};"
                 : "+f"(c[0]), "+f"(c[1]), "+f"(c[2]), "+f"(c[3])
                 : "r"(a[0]), "r"(a[1]), "r"(a[2]), "r"(a[3]), "r"(b0), "r"(b1));
}

__global__ __launch_bounds__(256, 2) void k_gemm(float4* __restrict__ out4) {
    extern __shared__ __half smem[];
    uint32_t sbase = smem_u32(smem);
    int tid = threadIdx.x, lane = tid & 31, wid = tid >> 5;

    // upper-triangle tile decode
    int t = blockIdx.x, by = 0;
    #pragma unroll 1
    for (int r = 0; r < NTB; r++) { int len = NTB - r; if (t < len) { by = r; break; } t -= len; }
    int bx = by + t;
    int bm = by * BM, bn = bx * BM;
    bool diag = (bx == by);

    // folded output zeroing (grid-stride over 16.7M float4)
    {
        float4 z = make_float4(0.f, 0.f, 0.f, 0.f);
        size_t n4 = (size_t)NROWS * NROWS / 4;
        size_t stride = (size_t)gridDim.x * 256;
        for (size_t i = (size_t)blockIdx.x * 256 + tid; i < n4; i += stride) out4[i] = z;
    }

    int wm0 = (wid >> 1) * 32;
    int wn0 = (wid & 1) * 64;
    int r0 = tid >> 2, s0 = tid & 3;
    int r1 = (tid + 256) >> 2, s1 = (tid + 256) & 3;
    const __half* gA = g_Bh + (size_t)bm * DDIM;
    const __half* gB = g_Bh + (size_t)bn * DDIM;

    float acc[2][8][4];
    #pragma unroll
    for (int mt = 0; mt < 2; mt++)
        #pragma unroll
        for (int nt = 0; nt < 8; nt++)
            #pragma unroll
            for (int i = 0; i < 4; i++) acc[mt][nt][i] = 0.f;

    #pragma unroll
    for (int s = 0; s < STAGES - 1; s++) {
        int k0 = s * BK;
        uint32_t sa = sbase + s * STAGE_BYTES;
        uint32_t sbm = sa + STAGE_HALF * 2;
        asm volatile("cp.async.cg.shared.global [%0], [%1], 16;" ::
                     "r"(sa + (r0 * SSTRIDE + s0 * 8) * 2), "l"(gA + (size_t)r0 * DDIM + k0 + s0 * 8));
        asm volatile("cp.async.cg.shared.global [%0], [%1], 16;" ::
                     "r"(sa + (r1 * SSTRIDE + s1 * 8) * 2), "l"(gA + (size_t)r1 * DDIM + k0 + s1 * 8));
        asm volatile("cp.async.cg.shared.global [%0], [%1], 16;" ::
                     "r"(sbm + (r0 * SSTRIDE + s0 * 8) * 2), "l"(gB + (size_t)r0 * DDIM + k0 + s0 * 8));
        asm volatile("cp.async.cg.shared.global [%0], [%1], 16;" ::
                     "r"(sbm + (r1 * SSTRIDE + s1 * 8) * 2), "l"(gB + (size_t)r1 * DDIM + k0 + s1 * 8));
        asm volatile("cp.async.commit_group;");
    }

    for (int i = 0; i < KITER; i++) {
        asm volatile("cp.async.wait_group %0;" :: "n"(STAGES - 2));
        __syncthreads();
        int st = i % STAGES;
        uint32_t As = sbase + st * STAGE_BYTES;
        uint32_t Bs = As + STAGE_HALF * 2;

        #pragma unroll
        for (int ks = 0; ks < 2; ks++) {
            uint32_t a[2][4];
            #pragma unroll
            for (int mt = 0; mt < 2; mt++)
                ldsm_x4(a[mt], As + ((wm0 + mt * 16 + (lane & 15)) * SSTRIDE + ks * 16 + (lane >> 4) * 8) * 2);
            #pragma unroll
            for (int ng = 0; ng < 4; ng++) {
                uint32_t b[4];
                ldsm_x4(b, Bs + ((wn0 + ng * 16 + (lane & 15)) * SSTRIDE + ks * 16 + (lane >> 4) * 8) * 2);
                #pragma unroll
                for (int mt = 0; mt < 2; mt++) {
                    mma16816(acc[mt][ng * 2 + 0], a[mt], b[0], b[2]);
                    mma16816(acc[mt][ng * 2 + 1], a[mt], b[1], b[3]);
                }
            }
        }

        int pf = i + STAGES - 1;
        if (pf < KITER) {
            int k0 = pf * BK;
            uint32_t sa = sbase + (pf % STAGES) * STAGE_BYTES;
            uint32_t sbm = sa + STAGE_HALF * 2;
            asm volatile("cp.async.cg.shared.global [%0], [%1], 16;" ::
                         "r"(sa + (r0 * SSTRIDE + s0 * 8) * 2), "l"(gA + (size_t)r0 * DDIM + k0 + s0 * 8));
            asm volatile("cp.async.cg.shared.global [%0], [%1], 16;" ::
                         "r"(sa + (r1 * SSTRIDE + s1 * 8) * 2), "l"(gA + (size_t)r1 * DDIM + k0 + s1 * 8));
            asm volatile("cp.async.cg.shared.global [%0], [%1], 16;" ::
                         "r"(sbm + (r0 * SSTRIDE + s0 * 8) * 2), "l"(gB + (size_t)r0 * DDIM + k0 + s0 * 8));
            asm volatile("cp.async.cg.shared.global [%0], [%1], 16;" ::
                         "r"(sbm + (r1 * SSTRIDE + s1 * 8) * 2), "l"(gB + (size_t)r1 * DDIM + k0 + s1 * 8));
        }
        asm volatile("cp.async.commit_group;");
        __syncthreads();
    }

    asm volatile("cp.async.wait_group 0;" ::);
    __syncthreads();

    char* smc = (char*)smem;
    uint32_t* smax = (uint32_t*)(smc + EP_SMAX);      // [128][2]
    if (tid < 256) smax[tid] = 0;
    __syncthreads();

    const float NEG_INF = __int_as_float(0xff800000);
    int gid = lane >> 2, tig = lane & 3;

    // ---- direct store (rows bm.., cols bn..) + row maxima of STORED halves ----
    #pragma unroll
    for (int mt = 0; mt < 2; mt++) {
        int row = bm + wm0 + mt * 16 + gid;
        float mx0 = NEG_INF, mx1 = NEG_INF;
        #pragma unroll
        for (int nt = 0; nt < 8; nt++) {
            int col = bn + wn0 + nt * 8 + 2 * tig;
            __half2 h0 = __floats2half2_rn(acc[mt][nt][0], acc[mt][nt][1]);
            __half2 h1 = __floats2half2_rn(acc[mt][nt][2], acc[mt][nt][3]);
            *(__half2*)(g_simh + (size_t)row * NROWS + col) = h0;
            *(__half2*)(g_simh + (size_t)(row + 8) * NROWS + col) = h1;
            float2 f0 = __half22float2(h0), f1 = __half22float2(h1);
            mx0 = fmaxf(mx0, fmaxf(f0.x, f0.y));
            mx1 = fmaxf(mx1, fmaxf(f1.x, f1.y));
        }
        mx0 = fmaxf(mx0, __shfl_xor_sync(0xffffffffu, mx0, 1));
        mx0 = fmaxf(mx0, __shfl_xor_sync(0xffffffffu, mx0, 2));
        mx1 = fmaxf(mx1, __shfl_xor_sync(0xffffffffu, mx1, 1));
        mx1 = fmaxf(mx1, __shfl_xor_sync(0xffffffffu, mx1, 2));
        if (tig == 0) {
            smax[(wm0 + mt * 16 + gid) * 2 + (wid & 1)] = fkey(mx0);
            smax[(wm0 + mt * 16 + 8 + gid) * 2 + (wid & 1)] = fkey(mx1);
        }
    }
    __syncthreads();
    if (tid < 128) {
        uint32_t k = max(smax[tid * 2], smax[tid * 2 + 1]);
        g_bmax[(size_t)(bm + tid) * NTB + bx] = k;
    }

    // ---- mirror (off-diagonal): transpose via smem, store rows bn.., cols bm.. ----
    if (!diag) {
        __half*   stage  = (__half*)(smc + EP_STAGE);     // [col][row] 128 x 136
        uint32_t* colmax = (uint32_t*)(smc + EP_COLMAX);  // [128]
        if (tid < 128) colmax[tid] = 0;
        __syncthreads();

        #pragma unroll
        for (int nt = 0; nt < 8; nt++) {
            #pragma unroll
            for (int e = 0; e < 2; e++) {
                int col = wn0 + nt * 8 + 2 * tig + e;       // 0..127 (tile col)
                float cm = NEG_INF;
                #pragma unroll
                for (int mt = 0; mt < 2; mt++) {
                    #pragma unroll
                    for (int h = 0; h < 2; h++) {
                        float v = acc[mt][nt][h * 2 + e];
                        __half hv = __float2half_rn(v);
                        int rowi = wm0 + mt * 16 + h * 8 + gid; // 0..127 (tile row)
                        stage[col * 136 + rowi] = hv;
                        cm = fmaxf(cm, __half2float(hv));
                    }
                }
                cm = fmaxf(cm, __shfl_xor_sync(0xffffffffu, cm, 4));
                cm = fmaxf(cm, __shfl_xor_sync(0xffffffffu, cm, 8));
                cm = fmaxf(cm, __shfl_xor_sync(0xffffffffu, cm, 16));
                if (gid == 0) atomicMax(&colmax[col], fkey(cm));
            }
        }
        __syncthreads();

        #pragma unroll
        for (int i = 0; i < 8; i++) {
            int c = tid + i * 256;
            int trow = c >> 4, tc = c & 15;
            uint4 v = *(uint4*)(stage + trow * 136 + tc * 8);
            *(uint4*)(g_simh + (size_t)(bn + trow) * NROWS + bm + tc * 8) = v;
        }
        if (tid < 128)
            g_bmax[(size_t)(bn + tid) * NTB + by] = colmax[tid];
    }
}

// ---------------- kernel 3: theta = 20th largest of 64 block maxima + block mask ----------------
__global__ __launch_bounds__(256) void k_theta() {
    int row = blockIdx.x * 8 + (threadIdx.x >> 5);
    int lane = threadIdx.x & 31;
    const uint32_t* bk = g_bmax + (size_t)row * NTB;
    uint32_t v0 = bk[lane], v1 = bk[lane + 32];
    uint32_t v0o = v0, v1o = v1;
    uint32_t M = 0;
    #pragma unroll 1
    for (int r = 0; r < 20; r++) {
        uint32_t lm = max(v0, v1);
        M = lm;
        #pragma unroll
        for (int off = 16; off; off >>= 1) M = max(M, __shfl_xor_sync(0xffffffffu, M, off));
        unsigned b = __ballot_sync(0xffffffffu, lm == M);
        if (lane == __ffs(b) - 1) { if (v0 == M) v0 = 0; else v1 = 0; }
    }
    unsigned m0 = __ballot_sync(0xffffffffu, v0o >= M);
    unsigned m1 = __ballot_sync(0xffffffffu, v1o >= M);
    if (lane == 0) {
        g_theta[row] = fkeyinv(M);
        g_bmask[row] = (unsigned long long)m0 | ((unsigned long long)m1 << 32);
    }
}

// ---------------- kernel 4: masked candidate gather + 8-lane-per-candidate exact
//                  rescore (coalesced) + exact top-10 ----------------
#define TCAP 512
__device__ __forceinline__ void topk_ins(float v, int j, float* bv, int* bi) {
    if (v > bv[KN - 1] || (v == bv[KN - 1] && j < bi[KN - 1])) {
        float cv = v; int ci = j;
        #pragma unroll
        for (int t = 0; t < KN; t++) {
            bool better = (cv > bv[t]) || (cv == bv[t] && ci < bi[t]);
            if (better) {
                float tv = bv[t]; int ti = bi[t];
                bv[t] = cv; bi[t] = ci;
                cv = tv; ci = ti;
            }
        }
    }
}
__device__ __forceinline__ void scan_block(int row, int b, int lane, float theta,
                                           int w, int* sli, int* scnt) {
    uint2 q = *(const uint2*)(g_simh + (size_t)row * NROWS + b * 128 + lane * 4);
    __half2 p0 = *(__half2*)&q.x, p1 = *(__half2*)&q.y;
    float2 f0 = __half22float2(p0), f1 = __half22float2(p1);
    float m = fmaxf(fmaxf(f0.x, f0.y), fmaxf(f1.x, f1.y));
    if (m >= theta) {
        int jb = b * 128 + lane * 4;
        if (f0.x >= theta) { int p = atomicAdd(&scnt[w], 1); if (p < TCAP) sli[p] = jb + 0; }
        if (f0.y >= theta) { int p = atomicAdd(&scnt[w], 1); if (p < TCAP) sli[p] = jb + 1; }
        if (f1.x >= theta) { int p = atomicAdd(&scnt[w], 1); if (p < TCAP) sli[p] = jb + 2; }
        if (f1.y >= theta) { int p = atomicAdd(&scnt[w], 1); if (p < TCAP) sli[p] = jb + 3; }
    }
}

__global__ __launch_bounds__(256) void k_topk(const float* __restrict__ feats) {
    __shared__ float slv[8][TCAP];
    __shared__ int   sli[8][TCAP];
    __shared__ int   scnt[8];
    int w = threadIdx.x >> 5, lane = threadIdx.x & 31;
    int row = blockIdx.x * 8 + w;
    const float NEG_INF = __int_as_float(0xff800000);
    float theta = g_theta[row];
    unsigned long long mask = g_bmask[row];
    if (lane == 0) scnt[w] = 0;
    __syncwarp();

    // scan only flagged blocks (>= theta can only occur where bmax >= theta)
    while (mask) {
        int b0 = __ffsll(mask) - 1; mask &= mask - 1;
        int b1 = -1;
        if (mask) { b1 = __ffsll(mask) - 1; mask &= mask - 1; }
        scan_block(row, b0, lane, theta, w, sli[w], scnt);
        if (b1 >= 0) scan_block(row, b1, lane, theta, w, sli[w], scnt);
    }
    __syncwarp();
    int cnt = scnt[w];

    float bv[KN]; int bi[KN];
    #pragma unroll
    for (int t = 0; t < KN; t++) { bv[t] = NEG_INF; bi[t] = 0x7fffffff; }

    const float4* fr = (const float4*)(feats + (size_t)row * DDIM);
    if (cnt <= TCAP) {
        // exact fp32 rescore, 8 lanes per candidate (4 candidates in flight per warp).
        // At step k the 8 sub-lanes read consecutive float4s of candidate row j:
        // 1 cache line per candidate per instruction (vs 32 for lane-per-candidate).
        int sl = lane & 7;        // sub-lane within candidate group
        int cs = lane >> 3;       // candidate slot 0..3
        float4 a[8];
        #pragma unroll
        for (int k = 0; k < 8; k++) a[k] = fr[k * 8 + sl];
        for (int base = 0; base < cnt; base += 4) {
            int i = base + cs;
            bool valid = (i < cnt);
            int j = sli[w][valid ? i : 0];
            const float4* fj = (const float4*)(feats + (size_t)j * DDIM);
            float s = 0.f;
            #pragma unroll
            for (int k = 0; k < 8; k++) {
                float4 b = fj[k * 8 + sl];
                s += a[k].x * b.x + a[k].y * b.y + a[k].z * b.z + a[k].w * b.w;
            }
            // reduce across the 8 sub-lanes (fixed order -> deterministic)
            s += __shfl_xor_sync(0xffffffffu, s, 1);
            s += __shfl_xor_sync(0xffffffffu, s, 2);
            s += __shfl_xor_sync(0xffffffffu, s, 4);
            if (valid && sl == 0) slv[w][i] = s * g_invn[j];
        }
        __syncwarp();
        for (int i = lane; i < cnt; i += 32) topk_ins(slv[w][i], sli[w][i], bv, bi);
    } else {
        // exact fallback (never expected): full exact rescore of the row
        for (int j = lane; j < NROWS; j += 32) {
            const float4* fj = (const float4*)(feats + (size_t)j * DDIM);
            float s = 0.f;
            #pragma unroll 8
            for (int k = 0; k < DDIM / 4; k++) {
                float4 va = fr[k], vb = fj[k];
                s += va.x * vb.x + va.y * vb.y + va.z * vb.z + va.w * vb.w;
            }
            topk_ins(s * g_invn[j], j, bv, bi);
        }
    }

    // 10 rounds of warp argmax ((v desc, idx asc) comparator) with pop
    #pragma unroll 1
    for (int r = 0; r < KN; r++) {
        float mv = bv[0]; int mi = bi[0];
        #pragma unroll
        for (int off = 16; off; off >>= 1) {
            float ov = __shfl_xor_sync(0xffffffffu, mv, off);
            int   oi = __shfl_xor_sync(0xffffffffu, mi, off);
            if (ov > mv || (ov == mv && oi < mi)) { mv = ov; mi = oi; }
        }
        if (mi == bi[0]) {
            #pragma unroll
            for (int t = 0; t < KN - 1; t++) { bv[t] = bv[t + 1]; bi[t] = bi[t + 1]; }
            bv[KN - 1] = NEG_INF; bi[KN - 1] = 0x7fffffff;
        }
        if (lane == 0) {
            g_topk[row * KN + r] = mi;
            atomicAdd(&g_dv[mi], 1);
        }
    }
}

// ---------------- kernel 5: inv_dv ----------------
__global__ void k_invdv() {
    int i = blockIdx.x * blockDim.x + threadIdx.x;
    if (i < NROWS) {
        int d = g_dv[i];
        g_invdv[i] = d > 0 ? 1.0f / sqrtf((float)d) : 0.0f;
    }
}

// ---------------- kernel 6: scatter 10x10 outer products per hyperedge ----------------
__global__ __launch_bounds__(128) void k_scatter(float* __restrict__ out) {
    __shared__ int   sidx[KN];
    __shared__ float sw[KN];
    int e = blockIdx.x;
    int t = threadIdx.x;
    if (t < KN) {
        int a = g_topk[e * KN + t];
        sidx[t] = a;
        sw[t] = g_invdv[a];
    }
    __syncthreads();
    if (t < KN * KN) {
        int a = sidx[t / KN];
        int b = sidx[t % KN];
        float val = (0.1f * sw[t / KN]) * sw[t % KN];
        atomicAdd(&out[(size_t)a * NROWS + b], val);
    }
}

// ---------------- launch ----------------
extern "C" void kernel_launch(void* const* d_in, const int* in_sizes, int n_in,
                              void* d_out, int out_size) {
    const float* feats = (const float*)d_in[0];
    float* out = (float*)d_out;

    k_prep<<<(NROWS * 32) / 256, 256>>>(feats);

    cudaFuncSetAttribute(k_gemm, cudaFuncAttributeMaxDynamicSharedMemorySize, GEMM_SMEM);
    k_gemm<<<NTRI, 256, GEMM_SMEM>>>((float4*)out);

    k_theta<<<NROWS / 8, 256>>>();
    k_topk<<<NROWS / 8, 256>>>(feats);
    k_invdv<<<NROWS / 256, 256>>>();
    k_scatter<<<NROWS, 128>>>(out);
}

// round 14
// speedup vs baseline: 1.6829x; 1.1000x over previous
#include <cuda_runtime.h>
#include <cuda_fp16.h>
#include <cstdint>

#define NROWS 8192
#define DDIM  256
#define KN    10
#define NTB   64                   // 128-col blocks per row

// ---------------- scratch (static device globals; no allocation) ----------------
__device__ __half    g_Bh[(size_t)NROWS * DDIM];     // fp16(feats/||feats||)
__device__ float     g_invn[NROWS];                  // 1/||feats||
__device__ __half    g_simh[(size_t)NROWS * NROWS];  // fp16 cos (symmetric, 128 MB)
__device__ uint32_t  g_bmax[(size_t)NROWS * NTB];    // per-128-col block maxima (monotone keys of STORED halves)
__device__ int       g_topk[NROWS * KN];
__device__ int       g_dv[NROWS];
__device__ float     g_invdv[NROWS];

__device__ __forceinline__ uint32_t smem_u32(const void* p) {
    uint32_t a;
    asm("{ .reg .u64 t; cvta.to.shared.u64 t, %1; cvt.u32.u64 %0, t; }" : "=r"(a) : "l"(p));
    return a;
}
// monotone float->uint key (total order incl. negatives)
__device__ __forceinline__ uint32_t fkey(float f) {
    uint32_t u = __float_as_uint(f);
    return (u & 0x80000000u) ? ~u : (u | 0x80000000u);
}
__device__ __forceinline__ float fkeyinv(uint32_t k) {
    return (k & 0x80000000u) ? __uint_as_float(k ^ 0x80000000u) : __uint_as_float(~k);
}

// ---------------- kernel 1: prep — norms, fp16 normalized rows; zero dv ----------------
__global__ __launch_bounds__(256) void k_prep(const float* __restrict__ feats) {
    int warp = (blockIdx.x * blockDim.x + threadIdx.x) >> 5;
    int lane = threadIdx.x & 31;
    if (warp < NROWS) {
        const float* x = feats + (size_t)warp * DDIM;
        float s = 0.f;
        #pragma unroll
        for (int k = lane; k < DDIM; k += 32) { float v = x[k]; s += v * v; }
        #pragma unroll
        for (int off = 16; off; off >>= 1) s += __shfl_xor_sync(0xffffffffu, s, off);
        float inv = 1.0f / sqrtf(s);
        if (lane == 0) g_invn[warp] = inv;
        __half* br = g_Bh + (size_t)warp * DDIM;
        #pragma unroll
        for (int k = lane; k < DDIM; k += 32)
            br[k] = __float2half(x[k] * inv);
    }
    int gt = blockIdx.x * blockDim.x + threadIdx.x;
    if (gt < NROWS) g_dv[gt] = 0;
}

// ---------------- kernel 2: symmetric HMMA GEMM (upper-triangle tiles + mirror),
//                  half store, block-max epilogue, folded output zeroing ----------------
#define BM 128
#define BK 32
#define STAGES 3
#define KITER (DDIM / BK)          // 8
#define SSTRIDE 40
#define STAGE_HALF (BM * SSTRIDE)
#define STAGE_BYTES (2 * STAGE_HALF * 2)
#define GEMM_SMEM (STAGES * STAGE_BYTES)   // 61440
#define NTRI (NTB * (NTB + 1) / 2)         // 2080
// epilogue smem offsets (bytes, within the same dynamic smem)
#define EP_STAGE   0                        // 128 x 136 halves = 34816
#define EP_COLMAX  34816                    // 128 u32 = 512
#define EP_SMAX    35840                    // 256 u32 = 1024

__device__ __forceinline__ void ldsm_x4(uint32_t* r, uint32_t addr) {
    asm volatile("ldmatrix.sync.aligned.m8n8.x4.shared.b16 {%0,%1,%2,%3}, [%4];"
                 : "=r"(r[0]), "=r"(r[1]), "=r"(r[2]), "=r"(r[3]) : "r"(addr));
}
__device__ __forceinline__ void mma16816(float* c, const uint32_t* a, uint32_t b0, uint32_t b1) {
    asm volatile("mma.sync.aligned.m16n8k16.row.col.f32.f16.f16.f32 "
                 "{%0,%1,%2,%3}, {%4,%5,%6,%7}, {%8,%9}, {%0,%1,%2,%3};"
                 : "+f"(c[0]), "+f"(c[1]), "+f"(c[2]), "+f"(c[3])
                 : "r"(a[0]), "r"(a[1]), "r"(a[2]), "r"(a[3]), "r"(b0), "r"(b1));
}

__global__ __launch_bounds__(256, 2) void k_gemm(float4* __restrict__ out4) {
    extern __shared__ __half smem[];
    uint32_t sbase = smem_u32(smem);
    int tid = threadIdx.x, lane = tid & 31, wid = tid >> 5;

    // upper-triangle tile decode
    int t = blockIdx.x, by = 0;
    #pragma unroll 1
    for (int r = 0; r < NTB; r++) { int len = NTB - r; if (t < len) { by = r; break; } t -= len; }
    int bx = by + t;
    int bm = by * BM, bn = bx * BM;
    bool diag = (bx == by);

    // folded output zeroing (grid-stride; streaming stores: not re-read until scatter)
    {
        float4 z = make_float4(0.f, 0.f, 0.f, 0.f);
        size_t n4 = (size_t)NROWS * NROWS / 4;
        size_t stride = (size_t)gridDim.x * 256;
        for (size_t i = (size_t)blockIdx.x * 256 + tid; i < n4; i += stride)
            __stcs(&out4[i], z);
    }

    int wm0 = (wid >> 1) * 32;
    int wn0 = (wid & 1) * 64;
    int r0 = tid >> 2, s0 = tid & 3;
    int r1 = (tid + 256) >> 2, s1 = (tid + 256) & 3;
    const __half* gA = g_Bh + (size_t)bm * DDIM;
    const __half* gB = g_Bh + (size_t)bn * DDIM;

    float acc[2][8][4];
    #pragma unroll
    for (int mt = 0; mt < 2; mt++)
        #pragma unroll
        for (int nt = 0; nt < 8; nt++)
            #pragma unroll
            for (int i = 0; i < 4; i++) acc[mt][nt][i] = 0.f;

    #pragma unroll
    for (int s = 0; s < STAGES - 1; s++) {
        int k0 = s * BK;
        uint32_t sa = sbase + s * STAGE_BYTES;
        uint32_t sbm = sa + STAGE_HALF * 2;
        asm volatile("cp.async.cg.shared.global [%0], [%1], 16;" ::
                     "r"(sa + (r0 * SSTRIDE + s0 * 8) * 2), "l"(gA + (size_t)r0 * DDIM + k0 + s0 * 8));
        asm volatile("cp.async.cg.shared.global [%0], [%1], 16;" ::
                     "r"(sa + (r1 * SSTRIDE + s1 * 8) * 2), "l"(gA + (size_t)r1 * DDIM + k0 + s1 * 8));
        asm volatile("cp.async.cg.shared.global [%0], [%1], 16;" ::
                     "r"(sbm + (r0 * SSTRIDE + s0 * 8) * 2), "l"(gB + (size_t)r0 * DDIM + k0 + s0 * 8));
        asm volatile("cp.async.cg.shared.global [%0], [%1], 16;" ::
                     "r"(sbm + (r1 * SSTRIDE + s1 * 8) * 2), "l"(gB + (size_t)r1 * DDIM + k0 + s1 * 8));
        asm volatile("cp.async.commit_group;");
    }

    for (int i = 0; i < KITER; i++) {
        asm volatile("cp.async.wait_group %0;" :: "n"(STAGES - 2));
        __syncthreads();
        int st = i % STAGES;
        uint32_t As = sbase + st * STAGE_BYTES;
        uint32_t Bs = As + STAGE_HALF * 2;

        #pragma unroll
        for (int ks = 0; ks < 2; ks++) {
            uint32_t a[2][4];
            #pragma unroll
            for (int mt = 0; mt < 2; mt++)
                ldsm_x4(a[mt], As + ((wm0 + mt * 16 + (lane & 15)) * SSTRIDE + ks * 16 + (lane >> 4) * 8) * 2);
            #pragma unroll
            for (int ng = 0; ng < 4; ng++) {
                uint32_t b[4];
                ldsm_x4(b, Bs + ((wn0 + ng * 16 + (lane & 15)) * SSTRIDE + ks * 16 + (lane >> 4) * 8) * 2);
                #pragma unroll
                for (int mt = 0; mt < 2; mt++) {
                    mma16816(acc[mt][ng * 2 + 0], a[mt], b[0], b[2]);
                    mma16816(acc[mt][ng * 2 + 1], a[mt], b[1], b[3]);
                }
            }
        }

        int pf = i + STAGES - 1;
        if (pf < KITER) {
            int k0 = pf * BK;
            uint32_t sa = sbase + (pf % STAGES) * STAGE_BYTES;
            uint32_t sbm = sa + STAGE_HALF * 2;
            asm volatile("cp.async.cg.shared.global [%0], [%1], 16;" ::
                         "r"(sa + (r0 * SSTRIDE + s0 * 8) * 2), "l"(gA + (size_t)r0 * DDIM + k0 + s0 * 8));
            asm volatile("cp.async.cg.shared.global [%0], [%1], 16;" ::
                         "r"(sa + (r1 * SSTRIDE + s1 * 8) * 2), "l"(gA + (size_t)r1 * DDIM + k0 + s1 * 8));
            asm volatile("cp.async.cg.shared.global [%0], [%1], 16;" ::
                         "r"(sbm + (r0 * SSTRIDE + s0 * 8) * 2), "l"(gB + (size_t)r0 * DDIM + k0 + s0 * 8));
            asm volatile("cp.async.cg.shared.global [%0], [%1], 16;" ::
                         "r"(sbm + (r1 * SSTRIDE + s1 * 8) * 2), "l"(gB + (size_t)r1 * DDIM + k0 + s1 * 8));
        }
        asm volatile("cp.async.commit_group;");
        __syncthreads();
    }

    asm volatile("cp.async.wait_group 0;" ::);
    __syncthreads();

    char* smc = (char*)smem;
    uint32_t* smax = (uint32_t*)(smc + EP_SMAX);      // [128][2]
    if (tid < 256) smax[tid] = 0;
    __syncthreads();

    const float NEG_INF = __int_as_float(0xff800000);
    int gid = lane >> 2, tig = lane & 3;

    // ---- direct store (rows bm.., cols bn..) + row maxima of STORED halves ----
    #pragma unroll
    for (int mt = 0; mt < 2; mt++) {
        int row = bm + wm0 + mt * 16 + gid;
        float mx0 = NEG_INF, mx1 = NEG_INF;
        #pragma unroll
        for (int nt = 0; nt < 8; nt++) {
            int col = bn + wn0 + nt * 8 + 2 * tig;
            __half2 h0 = __floats2half2_rn(acc[mt][nt][0], acc[mt][nt][1]);
            __half2 h1 = __floats2half2_rn(acc[mt][nt][2], acc[mt][nt][3]);
            *(__half2*)(g_simh + (size_t)row * NROWS + col) = h0;
            *(__half2*)(g_simh + (size_t)(row + 8) * NROWS + col) = h1;
            float2 f0 = __half22float2(h0), f1 = __half22float2(h1);
            mx0 = fmaxf(mx0, fmaxf(f0.x, f0.y));
            mx1 = fmaxf(mx1, fmaxf(f1.x, f1.y));
        }
        mx0 = fmaxf(mx0, __shfl_xor_sync(0xffffffffu, mx0, 1));
        mx0 = fmaxf(mx0, __shfl_xor_sync(0xffffffffu, mx0, 2));
        mx1 = fmaxf(mx1, __shfl_xor_sync(0xffffffffu, mx1, 1));
        mx1 = fmaxf(mx1, __shfl_xor_sync(0xffffffffu, mx1, 2));
        if (tig == 0) {
            smax[(wm0 + mt * 16 + gid) * 2 + (wid & 1)] = fkey(mx0);
            smax[(wm0 + mt * 16 + 8 + gid) * 2 + (wid & 1)] = fkey(mx1);
        }
    }
    __syncthreads();
    if (tid < 128) {
        uint32_t k = max(smax[tid * 2], smax[tid * 2 + 1]);
        g_bmax[(size_t)(bm + tid) * NTB + bx] = k;
    }

    // ---- mirror (off-diagonal): transpose via smem, store rows bn.., cols bm.. ----
    if (!diag) {
        __half*   stage  = (__half*)(smc + EP_STAGE);     // [col][row] 128 x 136
        uint32_t* colmax = (uint32_t*)(smc + EP_COLMAX);  // [128]
        if (tid < 128) colmax[tid] = 0;
        __syncthreads();

        #pragma unroll
        for (int nt = 0; nt < 8; nt++) {
            #pragma unroll
            for (int e = 0; e < 2; e++) {
                int col = wn0 + nt * 8 + 2 * tig + e;       // 0..127 (tile col)
                float cm = NEG_INF;
                #pragma unroll
                for (int mt = 0; mt < 2; mt++) {
                    #pragma unroll
                    for (int h = 0; h < 2; h++) {
                        float v = acc[mt][nt][h * 2 + e];
                        __half hv = __float2half_rn(v);
                        int rowi = wm0 + mt * 16 + h * 8 + gid; // 0..127 (tile row)
                        stage[col * 136 + rowi] = hv;
                        cm = fmaxf(cm, __half2float(hv));
                    }
                }
                cm = fmaxf(cm, __shfl_xor_sync(0xffffffffu, cm, 4));
                cm = fmaxf(cm, __shfl_xor_sync(0xffffffffu, cm, 8));
                cm = fmaxf(cm, __shfl_xor_sync(0xffffffffu, cm, 16));
                if (gid == 0) atomicMax(&colmax[col], fkey(cm));
            }
        }
        __syncthreads();

        #pragma unroll
        for (int i = 0; i < 8; i++) {
            int c = tid + i * 256;
            int trow = c >> 4, tc = c & 15;
            uint4 v = *(uint4*)(stage + trow * 136 + tc * 8);
            *(uint4*)(g_simh + (size_t)(bn + trow) * NROWS + bm + tc * 8) = v;
        }
        if (tid < 128)
            g_bmax[(size_t)(bn + tid) * NTB + by] = colmax[tid];
    }
}

// ---------------- kernel 3: fused per-warp theta + masked gather +
//                  8-lane-per-candidate exact rescore + exact top-10 ----------------
#define TCAP 512
__device__ __forceinline__ void topk_ins(float v, int j, float* bv, int* bi) {
    if (v > bv[KN - 1] || (v == bv[KN - 1] && j < bi[KN - 1])) {
        float cv = v; int ci = j;
        #pragma unroll
        for (int t = 0; t < KN; t++) {
            bool better = (cv > bv[t]) || (cv == bv[t] && ci < bi[t]);
            if (better) {
                float tv = bv[t]; int ti = bi[t];
                bv[t] = cv; bi[t] = ci;
                cv = tv; ci = ti;
            }
        }
    }
}
__device__ __forceinline__ void scan_block(int row, int b, int lane, float theta,
                                           int w, int* sli, int* scnt) {
    uint2 q = *(const uint2*)(g_simh + (size_t)row * NROWS + b * 128 + lane * 4);
    __half2 p0 = *(__half2*)&q.x, p1 = *(__half2*)&q.y;
    float2 f0 = __half22float2(p0), f1 = __half22float2(p1);
    float m = fmaxf(fmaxf(f0.x, f0.y), fmaxf(f1.x, f1.y));
    if (m >= theta) {
        int jb = b * 128 + lane * 4;
        if (f0.x >= theta) { int p = atomicAdd(&scnt[w], 1); if (p < TCAP) sli[p] = jb + 0; }
        if (f0.y >= theta) { int p = atomicAdd(&scnt[w], 1); if (p < TCAP) sli[p] = jb + 1; }
        if (f1.x >= theta) { int p = atomicAdd(&scnt[w], 1); if (p < TCAP) sli[p] = jb + 2; }
        if (f1.y >= theta) { int p = atomicAdd(&scnt[w], 1); if (p < TCAP) sli[p] = jb + 3; }
    }
}

__global__ __launch_bounds__(256) void k_topk(const float* __restrict__ feats) {
    __shared__ float slv[8][TCAP];
    __shared__ int   sli[8][TCAP];
    __shared__ int   scnt[8];
    int w = threadIdx.x >> 5, lane = threadIdx.x & 31;
    int row = blockIdx.x * 8 + w;
    const float NEG_INF = __int_as_float(0xff800000);
    if (lane == 0) scnt[w] = 0;

    // fused theta: 20th largest of the row's 64 block maxima + flagged-block mask
    float theta;
    unsigned long long mask;
    {
        const uint32_t* bk = g_bmax + (size_t)row * NTB;
        uint32_t v0 = bk[lane], v1 = bk[lane + 32];
        uint32_t v0o = v0, v1o = v1, M = 0;
        #pragma unroll 1
        for (int r = 0; r < 20; r++) {
            uint32_t lm = max(v0, v1);
            M = lm;
            #pragma unroll
            for (int off = 16; off; off >>= 1) M = max(M, __shfl_xor_sync(0xffffffffu, M, off));
            unsigned b = __ballot_sync(0xffffffffu, lm == M);
            if (lane == __ffs(b) - 1) { if (v0 == M) v0 = 0; else v1 = 0; }
        }
        unsigned m0 = __ballot_sync(0xffffffffu, v0o >= M);
        unsigned m1 = __ballot_sync(0xffffffffu, v1o >= M);
        theta = fkeyinv(M);
        mask = (unsigned long long)m0 | ((unsigned long long)m1 << 32);
    }
    __syncwarp();

    // scan only flagged blocks, 4 per iteration (MLP=4)
    while (mask) {
        int b0 = __ffsll(mask) - 1; mask &= mask - 1;
        int b1 = -1, b2 = -1, b3 = -1;
        if (mask) { b1 = __ffsll(mask) - 1; mask &= mask - 1; }
        if (mask) { b2 = __ffsll(mask) - 1; mask &= mask - 1; }
        if (mask) { b3 = __ffsll(mask) - 1; mask &= mask - 1; }
        scan_block(row, b0, lane, theta, w, sli[w], scnt);
        if (b1 >= 0) scan_block(row, b1, lane, theta, w, sli[w], scnt);
        if (b2 >= 0) scan_block(row, b2, lane, theta, w, sli[w], scnt);
        if (b3 >= 0) scan_block(row, b3, lane, theta, w, sli[w], scnt);
    }
    __syncwarp();
    int cnt = scnt[w];

    float bv[KN]; int bi[KN];
    #pragma unroll
    for (int t = 0; t < KN; t++) { bv[t] = NEG_INF; bi[t] = 0x7fffffff; }

    const float4* fr = (const float4*)(feats + (size_t)row * DDIM);
    if (cnt <= TCAP) {
        // exact fp32 rescore, 8 lanes per candidate (4 candidates in flight per warp)
        int sl = lane & 7;        // sub-lane within candidate group
        int cs = lane >> 3;       // candidate slot 0..3
        float4 a[8];
        #pragma unroll
        for (int k = 0; k < 8; k++) a[k] = fr[k * 8 + sl];
        for (int base = 0; base < cnt; base += 4) {
            int i = base + cs;
            bool valid = (i < cnt);
            int j = sli[w][valid ? i : 0];
            const float4* fj = (const float4*)(feats + (size_t)j * DDIM);
            float s = 0.f;
            #pragma unroll
            for (int k = 0; k < 8; k++) {
                float4 b = fj[k * 8 + sl];
                s += a[k].x * b.x + a[k].y * b.y + a[k].z * b.z + a[k].w * b.w;
            }
            s += __shfl_xor_sync(0xffffffffu, s, 1);
            s += __shfl_xor_sync(0xffffffffu, s, 2);
            s += __shfl_xor_sync(0xffffffffu, s, 4);
            if (valid && sl == 0) slv[w][i] = s * g_invn[j];
        }
        __syncwarp();
        for (int i = lane; i < cnt; i += 32) topk_ins(slv[w][i], sli[w][i], bv, bi);
    } else {
        // exact fallback (never expected): full exact rescore of the row
        for (int j = lane; j < NROWS; j += 32) {
            const float4* fj = (const float4*)(feats + (size_t)j * DDIM);
            float s = 0.f;
            #pragma unroll 8
            for (int k = 0; k < DDIM / 4; k++) {
                float4 va = fr[k], vb = fj[k];
                s += va.x * vb.x + va.y * vb.y + va.z * vb.z + va.w * vb.w;
            }
            topk_ins(s * g_invn[j], j, bv, bi);
        }
    }

    // 10 rounds of warp argmax ((v desc, idx asc) comparator) with pop
    #pragma unroll 1
    for (int r = 0; r < KN; r++) {
        float mv = bv[0]; int mi = bi[0];
        #pragma unroll
        for (int off = 16; off; off >>= 1) {
            float ov = __shfl_xor_sync(0xffffffffu, mv, off);
            int   oi = __shfl_xor_sync(0xffffffffu, mi, off);
            if (ov > mv || (ov == mv && oi < mi)) { mv = ov; mi = oi; }
        }
        if (mi == bi[0]) {
            #pragma unroll
            for (int t = 0; t < KN - 1; t++) { bv[t] = bv[t + 1]; bi[t] = bi[t + 1]; }
            bv[KN - 1] = NEG_INF; bi[KN - 1] = 0x7fffffff;
        }
        if (lane == 0) {
            g_topk[row * KN + r] = mi;
            atomicAdd(&g_dv[mi], 1);
        }
    }
}

// ---------------- kernel 4: inv_dv ----------------
__global__ void k_invdv() {
    int i = blockIdx.x * blockDim.x + threadIdx.x;
    if (i < NROWS) {
        int d = g_dv[i];
        g_invdv[i] = d > 0 ? 1.0f / sqrtf((float)d) : 0.0f;
    }
}

// ---------------- kernel 5: scatter 10x10 outer products per hyperedge ----------------
__global__ __launch_bounds__(128) void k_scatter(float* __restrict__ out) {
    __shared__ int   sidx[KN];
    __shared__ float sw[KN];
    int e = blockIdx.x;
    int t = threadIdx.x;
    if (t < KN) {
        int a = g_topk[e * KN + t];
        sidx[t] = a;
        sw[t] = g_invdv[a];
    }
    __syncthreads();
    if (t < KN * KN) {
        int a = sidx[t / KN];
        int b = sidx[t % KN];
        float val = (0.1f * sw[t / KN]) * sw[t % KN];
        atomicAdd(&out[(size_t)a * NROWS + b], val);
    }
}

// ---------------- launch ----------------
extern "C" void kernel_launch(void* const* d_in, const int* in_sizes, int n_in,
                              void* d_out, int out_size) {
    const float* feats = (const float*)d_in[0];
    float* out = (float*)d_out;

    k_prep<<<(NROWS * 32) / 256, 256>>>(feats);

    cudaFuncSetAttribute(k_gemm, cudaFuncAttributeMaxDynamicSharedMemorySize, GEMM_SMEM);
    k_gemm<<<NTRI, 256, GEMM_SMEM>>>((float4*)out);

    k_topk<<<NROWS / 8, 256>>>(feats);
    k_invdv<<<NROWS / 256, 256>>>();
    k_scatter<<<NROWS, 128>>>(out);
}

// round 15
// speedup vs baseline: 1.7738x; 1.0540x over previous
#include <cuda_runtime.h>
#include <cuda_fp16.h>
#include <cstdint>

#define NROWS 8192
#define DDIM  256
#define KN    10
#define NTB   64                   // 128-col blocks per row

// ---------------- scratch (static device globals; no allocation) ----------------
__device__ __half    g_Bh[(size_t)NROWS * DDIM];     // fp16(feats/||feats||)
__device__ float     g_invn[NROWS];                  // 1/||feats||
__device__ __half    g_simh[(size_t)NROWS * NROWS];  // fp16 cos (symmetric, 128 MB)
__device__ uint32_t  g_bmax[(size_t)NROWS * NTB];    // per-128-col block maxima (monotone keys of STORED halves)
__device__ int       g_topk[NROWS * KN];
__device__ int       g_dv[NROWS];

__device__ __forceinline__ uint32_t smem_u32(const void* p) {
    uint32_t a;
    asm("{ .reg .u64 t; cvta.to.shared.u64 t, %1; cvt.u32.u64 %0, t; }" : "=r"(a) : "l"(p));
    return a;
}
// monotone float->uint key (total order incl. negatives)
__device__ __forceinline__ uint32_t fkey(float f) {
    uint32_t u = __float_as_uint(f);
    return (u & 0x80000000u) ? ~u : (u | 0x80000000u);
}
__device__ __forceinline__ float fkeyinv(uint32_t k) {
    return (k & 0x80000000u) ? __uint_as_float(k ^ 0x80000000u) : __uint_as_float(~k);
}

// ---------------- kernel 1: prep — norms, fp16 normalized rows; zero dv ----------------
__global__ __launch_bounds__(256) void k_prep(const float* __restrict__ feats) {
    int warp = (blockIdx.x * blockDim.x + threadIdx.x) >> 5;
    int lane = threadIdx.x & 31;
    if (warp < NROWS) {
        const float* x = feats + (size_t)warp * DDIM;
        float s = 0.f;
        #pragma unroll
        for (int k = lane; k < DDIM; k += 32) { float v = x[k]; s += v * v; }
        #pragma unroll
        for (int off = 16; off; off >>= 1) s += __shfl_xor_sync(0xffffffffu, s, off);
        float inv = 1.0f / sqrtf(s);
        if (lane == 0) g_invn[warp] = inv;
        __half* br = g_Bh + (size_t)warp * DDIM;
        #pragma unroll
        for (int k = lane; k < DDIM; k += 32)
            br[k] = __float2half(x[k] * inv);
    }
    int gt = blockIdx.x * blockDim.x + threadIdx.x;
    if (gt < NROWS) g_dv[gt] = 0;
}

// ---------------- kernel 2: symmetric HMMA GEMM (upper-triangle tiles + mirror),
//                  half store (staged, streaming), block-max epilogue, folded zeroing ----------------
#define BM 128
#define BK 32
#define STAGES 4
#define KITER (DDIM / BK)          // 8
#define SSTRIDE 40
#define STAGE_HALF (BM * SSTRIDE)
#define STAGE_BYTES (2 * STAGE_HALF * 2)
#define GEMM_SMEM (STAGES * STAGE_BYTES)   // 81920
#define NTRI (NTB * (NTB + 1) / 2)         // 2080
// epilogue smem offsets (bytes, within the same dynamic smem; reused after mainloop)
#define EP_STAGE   0                        // 128 x 136 halves = 34816
#define EP_COLMAX  34816                    // 128 u32 = 512
#define EP_SMAX    35840                    // 256 u32 = 1024

__device__ __forceinline__ void ldsm_x4(uint32_t* r, uint32_t addr) {
    asm volatile("ldmatrix.sync.aligned.m8n8.x4.shared.b16 {%0,%1,%2,%3}, [%4];"
                 : "=r"(r[0]), "=r"(r[1]), "=r"(r[2]), "=r"(r[3]) : "r"(addr));
}
__device__ __forceinline__ void mma16816(float* c, const uint32_t* a, uint32_t b0, uint32_t b1) {
    asm volatile("mma.sync.aligned.m16n8k16.row.col.f32.f16.f16.f32 "
                 "{%0,%1,%2,%3}, {%4,%5,%6,%7}, {%8,%9}, {%0,%1,%2,%3};"
                 : "+f"(c[0]), "+f"(c[1]), "+f"(c[2]), "+f"(c[3])
                 : "r"(a[0]), "r"(a[1]), "r"(a[2]), "r"(a[3]), "r"(b0), "r"(b1));
}
__device__ __forceinline__ void stg_cs_u4(void* p, uint4 v) {
    asm volatile("st.global.cs.v4.u32 [%0], {%1,%2,%3,%4};"
                 :: "l"(p), "r"(v.x), "r"(v.y), "r"(v.z), "r"(v.w) : "memory");
}

__global__ __launch_bounds__(256, 2) void k_gemm(float4* __restrict__ out4) {
    extern __shared__ __half smem[];
    uint32_t sbase = smem_u32(smem);
    int tid = threadIdx.x, lane = tid & 31, wid = tid >> 5;

    // upper-triangle tile decode
    int t = blockIdx.x, by = 0;
    #pragma unroll 1
    for (int r = 0; r < NTB; r++) { int len = NTB - r; if (t < len) { by = r; break; } t -= len; }
    int bx = by + t;
    int bm = by * BM, bn = bx * BM;
    bool diag = (bx == by);

    // folded output zeroing (grid-stride; streaming stores: not re-read until scatter)
    {
        float4 z = make_float4(0.f, 0.f, 0.f, 0.f);
        size_t n4 = (size_t)NROWS * NROWS / 4;
        size_t stride = (size_t)gridDim.x * 256;
        for (size_t i = (size_t)blockIdx.x * 256 + tid; i < n4; i += stride)
            __stcs(&out4[i], z);
    }

    int wm0 = (wid >> 1) * 32;
    int wn0 = (wid & 1) * 64;
    int r0 = tid >> 2, s0 = tid & 3;
    int r1 = (tid + 256) >> 2, s1 = (tid + 256) & 3;
    const __half* gA = g_Bh + (size_t)bm * DDIM;
    const __half* gB = g_Bh + (size_t)bn * DDIM;

    float acc[2][8][4];
    #pragma unroll
    for (int mt = 0; mt < 2; mt++)
        #pragma unroll
        for (int nt = 0; nt < 8; nt++)
            #pragma unroll
            for (int i = 0; i < 4; i++) acc[mt][nt][i] = 0.f;

    #pragma unroll
    for (int s = 0; s < STAGES - 1; s++) {
        int k0 = s * BK;
        uint32_t sa = sbase + s * STAGE_BYTES;
        uint32_t sbm = sa + STAGE_HALF * 2;
        asm volatile("cp.async.cg.shared.global [%0], [%1], 16;" ::
                     "r"(sa + (r0 * SSTRIDE + s0 * 8) * 2), "l"(gA + (size_t)r0 * DDIM + k0 + s0 * 8));
        asm volatile("cp.async.cg.shared.global [%0], [%1], 16;" ::
                     "r"(sa + (r1 * SSTRIDE + s1 * 8) * 2), "l"(gA + (size_t)r1 * DDIM + k0 + s1 * 8));
        asm volatile("cp.async.cg.shared.global [%0], [%1], 16;" ::
                     "r"(sbm + (r0 * SSTRIDE + s0 * 8) * 2), "l"(gB + (size_t)r0 * DDIM + k0 + s0 * 8));
        asm volatile("cp.async.cg.shared.global [%0], [%1], 16;" ::
                     "r"(sbm + (r1 * SSTRIDE + s1 * 8) * 2), "l"(gB + (size_t)r1 * DDIM + k0 + s1 * 8));
        asm volatile("cp.async.commit_group;");
    }

    for (int i = 0; i < KITER; i++) {
        asm volatile("cp.async.wait_group %0;" :: "n"(STAGES - 2));
        __syncthreads();
        int st = i % STAGES;
        uint32_t As = sbase + st * STAGE_BYTES;
        uint32_t Bs = As + STAGE_HALF * 2;

        #pragma unroll
        for (int ks = 0; ks < 2; ks++) {
            uint32_t a[2][4];
            #pragma unroll
            for (int mt = 0; mt < 2; mt++)
                ldsm_x4(a[mt], As + ((wm0 + mt * 16 + (lane & 15)) * SSTRIDE + ks * 16 + (lane >> 4) * 8) * 2);
            #pragma unroll
            for (int ng = 0; ng < 4; ng++) {
                uint32_t b[4];
                ldsm_x4(b, Bs + ((wn0 + ng * 16 + (lane & 15)) * SSTRIDE + ks * 16 + (lane >> 4) * 8) * 2);
                #pragma unroll
                for (int mt = 0; mt < 2; mt++) {
                    mma16816(acc[mt][ng * 2 + 0], a[mt], b[0], b[2]);
                    mma16816(acc[mt][ng * 2 + 1], a[mt], b[1], b[3]);
                }
            }
        }

        int pf = i + STAGES - 1;
        if (pf < KITER) {
            int k0 = pf * BK;
            uint32_t sa = sbase + (pf % STAGES) * STAGE_BYTES;
            uint32_t sbm = sa + STAGE_HALF * 2;
            asm volatile("cp.async.cg.shared.global [%0], [%1], 16;" ::
                         "r"(sa + (r0 * SSTRIDE + s0 * 8) * 2), "l"(gA + (size_t)r0 * DDIM + k0 + s0 * 8));
            asm volatile("cp.async.cg.shared.global [%0], [%1], 16;" ::
                         "r"(sa + (r1 * SSTRIDE + s1 * 8) * 2), "l"(gA + (size_t)r1 * DDIM + k0 + s1 * 8));
            asm volatile("cp.async.cg.shared.global [%0], [%1], 16;" ::
                         "r"(sbm + (r0 * SSTRIDE + s0 * 8) * 2), "l"(gB + (size_t)r0 * DDIM + k0 + s0 * 8));
            asm volatile("cp.async.cg.shared.global [%0], [%1], 16;" ::
                         "r"(sbm + (r1 * SSTRIDE + s1 * 8) * 2), "l"(gB + (size_t)r1 * DDIM + k0 + s1 * 8));
        }
        asm volatile("cp.async.commit_group;");
        __syncthreads();
    }

    asm volatile("cp.async.wait_group 0;" ::);
    __syncthreads();

    char* smc = (char*)smem;
    __half*   stage  = (__half*)(smc + EP_STAGE);     // 128 x 136 halves
    uint32_t* smax = (uint32_t*)(smc + EP_SMAX);      // [128][2]
    if (tid < 256) smax[tid] = 0;
    __syncthreads();

    const float NEG_INF = __int_as_float(0xff800000);
    int gid = lane >> 2, tig = lane & 3;

    // ---- direct tile: stage [row][col] into smem + row maxima of STORED halves ----
    #pragma unroll
    for (int mt = 0; mt < 2; mt++) {
        float mx0 = NEG_INF, mx1 = NEG_INF;
        int r0i = wm0 + mt * 16 + gid;        // tile row for c0,c1
        int r1i = r0i + 8;                    // tile row for c2,c3
        #pragma unroll
        for (int nt = 0; nt < 8; nt++) {
            int col = wn0 + nt * 8 + 2 * tig;
            __half2 h0 = __floats2half2_rn(acc[mt][nt][0], acc[mt][nt][1]);
            __half2 h1 = __floats2half2_rn(acc[mt][nt][2], acc[mt][nt][3]);
            *(__half2*)(stage + r0i * 136 + col) = h0;
            *(__half2*)(stage + r1i * 136 + col) = h1;
            float2 f0 = __half22float2(h0), f1 = __half22float2(h1);
            mx0 = fmaxf(mx0, fmaxf(f0.x, f0.y));
            mx1 = fmaxf(mx1, fmaxf(f1.x, f1.y));
        }
        mx0 = fmaxf(mx0, __shfl_xor_sync(0xffffffffu, mx0, 1));
        mx0 = fmaxf(mx0, __shfl_xor_sync(0xffffffffu, mx0, 2));
        mx1 = fmaxf(mx1, __shfl_xor_sync(0xffffffffu, mx1, 1));
        mx1 = fmaxf(mx1, __shfl_xor_sync(0xffffffffu, mx1, 2));
        if (tig == 0) {
            smax[r0i * 2 + (wid & 1)] = fkey(mx0);
            smax[r1i * 2 + (wid & 1)] = fkey(mx1);
        }
    }
    __syncthreads();
    if (tid < 128) {
        uint32_t k = max(smax[tid * 2], smax[tid * 2 + 1]);
        g_bmax[(size_t)(bm + tid) * NTB + bx] = k;
    }
    // coalesced streaming store of the direct tile (2048 x 16B)
    #pragma unroll
    for (int i = 0; i < 8; i++) {
        int c = tid + i * 256;
        int trow = c >> 4, tc = c & 15;
        uint4 v = *(uint4*)(stage + trow * 136 + tc * 8);
        stg_cs_u4(g_simh + (size_t)(bm + trow) * NROWS + bn + tc * 8, v);
    }

    // ---- mirror (off-diagonal): transpose via smem, store rows bn.., cols bm.. ----
    if (!diag) {
        uint32_t* colmax = (uint32_t*)(smc + EP_COLMAX);  // [128]
        __syncthreads();      // direct-tile reads of stage done before overwrite
        if (tid < 128) colmax[tid] = 0;
        __syncthreads();

        #pragma unroll
        for (int nt = 0; nt < 8; nt++) {
            #pragma unroll
            for (int e = 0; e < 2; e++) {
                int col = wn0 + nt * 8 + 2 * tig + e;       // 0..127 (tile col)
                float cm = NEG_INF;
                #pragma unroll
                for (int mt = 0; mt < 2; mt++) {
                    #pragma unroll
                    for (int h = 0; h < 2; h++) {
                        float v = acc[mt][nt][h * 2 + e];
                        __half hv = __float2half_rn(v);
                        int rowi = wm0 + mt * 16 + h * 8 + gid; // 0..127 (tile row)
                        stage[col * 136 + rowi] = hv;
                        cm = fmaxf(cm, __half2float(hv));
                    }
                }
                cm = fmaxf(cm, __shfl_xor_sync(0xffffffffu, cm, 4));
                cm = fmaxf(cm, __shfl_xor_sync(0xffffffffu, cm, 8));
                cm = fmaxf(cm, __shfl_xor_sync(0xffffffffu, cm, 16));
                if (gid == 0) atomicMax(&colmax[col], fkey(cm));
            }
        }
        __syncthreads();

        #pragma unroll
        for (int i = 0; i < 8; i++) {
            int c = tid + i * 256;
            int trow = c >> 4, tc = c & 15;
            uint4 v = *(uint4*)(stage + trow * 136 + tc * 8);
            stg_cs_u4(g_simh + (size_t)(bn + trow) * NROWS + bm + tc * 8, v);
        }
        if (tid < 128)
            g_bmax[(size_t)(bn + tid) * NTB + by] = colmax[tid];
    }
}

// ---------------- kernel 3: fused per-warp theta + masked gather +
//                  8-lane-per-candidate exact rescore + exact top-10 ----------------
#define TCAP 512
__device__ __forceinline__ void topk_ins(float v, int j, float* bv, int* bi) {
    if (v > bv[KN - 1] || (v == bv[KN - 1] && j < bi[KN - 1])) {
        float cv = v; int ci = j;
        #pragma unroll
        for (int t = 0; t < KN; t++) {
            bool better = (cv > bv[t]) || (cv == bv[t] && ci < bi[t]);
            if (better) {
                float tv = bv[t]; int ti = bi[t];
                bv[t] = cv; bi[t] = ci;
                cv = tv; ci = ti;
            }
        }
    }
}
__device__ __forceinline__ void scan_block(int row, int b, int lane, float theta,
                                           int w, int* sli, int* scnt) {
    uint2 q = *(const uint2*)(g_simh + (size_t)row * NROWS + b * 128 + lane * 4);
    __half2 p0 = *(__half2*)&q.x, p1 = *(__half2*)&q.y;
    float2 f0 = __half22float2(p0), f1 = __half22float2(p1);
    float m = fmaxf(fmaxf(f0.x, f0.y), fmaxf(f1.x, f1.y));
    if (m >= theta) {
        int jb = b * 128 + lane * 4;
        if (f0.x >= theta) { int p = atomicAdd(&scnt[w], 1); if (p < TCAP) sli[p] = jb + 0; }
        if (f0.y >= theta) { int p = atomicAdd(&scnt[w], 1); if (p < TCAP) sli[p] = jb + 1; }
        if (f1.x >= theta) { int p = atomicAdd(&scnt[w], 1); if (p < TCAP) sli[p] = jb + 2; }
        if (f1.y >= theta) { int p = atomicAdd(&scnt[w], 1); if (p < TCAP) sli[p] = jb + 3; }
    }
}

__global__ __launch_bounds__(256) void k_topk(const float* __restrict__ feats) {
    __shared__ float slv[8][TCAP];
    __shared__ int   sli[8][TCAP];
    __shared__ int   scnt[8];
    int w = threadIdx.x >> 5, lane = threadIdx.x & 31;
    int row = blockIdx.x * 8 + w;
    const float NEG_INF = __int_as_float(0xff800000);
    if (lane == 0) scnt[w] = 0;

    // fused theta: 20th largest of the row's 64 block maxima + flagged-block mask
    float theta;
    unsigned long long mask;
    {
        const uint32_t* bk = g_bmax + (size_t)row * NTB;
        uint32_t v0 = bk[lane], v1 = bk[lane + 32];
        uint32_t v0o = v0, v1o = v1, M = 0;
        #pragma unroll 1
        for (int r = 0; r < 20; r++) {
            uint32_t lm = max(v0, v1);
            M = lm;
            #pragma unroll
            for (int off = 16; off; off >>= 1) M = max(M, __shfl_xor_sync(0xffffffffu, M, off));
            unsigned b = __ballot_sync(0xffffffffu, lm == M);
            if (lane == __ffs(b) - 1) { if (v0 == M) v0 = 0; else v1 = 0; }
        }
        unsigned m0 = __ballot_sync(0xffffffffu, v0o >= M);
        unsigned m1 = __ballot_sync(0xffffffffu, v1o >= M);
        theta = fkeyinv(M);
        mask = (unsigned long long)m0 | ((unsigned long long)m1 << 32);
    }
    __syncwarp();

    // scan only flagged blocks, 4 per iteration (MLP=4)
    while (mask) {
        int b0 = __ffsll(mask) - 1; mask &= mask - 1;
        int b1 = -1, b2 = -1, b3 = -1;
        if (mask) { b1 = __ffsll(mask) - 1; mask &= mask - 1; }
        if (mask) { b2 = __ffsll(mask) - 1; mask &= mask - 1; }
        if (mask) { b3 = __ffsll(mask) - 1; mask &= mask - 1; }
        scan_block(row, b0, lane, theta, w, sli[w], scnt);
        if (b1 >= 0) scan_block(row, b1, lane, theta, w, sli[w], scnt);
        if (b2 >= 0) scan_block(row, b2, lane, theta, w, sli[w], scnt);
        if (b3 >= 0) scan_block(row, b3, lane, theta, w, sli[w], scnt);
    }
    __syncwarp();
    int cnt = scnt[w];

    float bv[KN]; int bi[KN];
    #pragma unroll
    for (int t = 0; t < KN; t++) { bv[t] = NEG_INF; bi[t] = 0x7fffffff; }

    const float4* fr = (const float4*)(feats + (size_t)row * DDIM);
    if (cnt <= TCAP) {
        // exact fp32 rescore, 8 lanes per candidate (4 candidates in flight per warp)
        int sl = lane & 7;        // sub-lane within candidate group
        int cs = lane >> 3;       // candidate slot 0..3
        float4 a[8];
        #pragma unroll
        for (int k = 0; k < 8; k++) a[k] = fr[k * 8 + sl];
        for (int base = 0; base < cnt; base += 4) {
            int i = base + cs;
            bool valid = (i < cnt);
            int j = sli[w][valid ? i : 0];
            const float4* fj = (const float4*)(feats + (size_t)j * DDIM);
            float s = 0.f;
            #pragma unroll
            for (int k = 0; k < 8; k++) {
                float4 b = fj[k * 8 + sl];
                s += a[k].x * b.x + a[k].y * b.y + a[k].z * b.z + a[k].w * b.w;
            }
            s += __shfl_xor_sync(0xffffffffu, s, 1);
            s += __shfl_xor_sync(0xffffffffu, s, 2);
            s += __shfl_xor_sync(0xffffffffu, s, 4);
            if (valid && sl == 0) slv[w][i] = s * g_invn[j];
        }
        __syncwarp();
        for (int i = lane; i < cnt; i += 32) topk_ins(slv[w][i], sli[w][i], bv, bi);
    } else {
        // exact fallback (never expected): full exact rescore of the row
        for (int j = lane; j < NROWS; j += 32) {
            const float4* fj = (const float4*)(feats + (size_t)j * DDIM);
            float s = 0.f;
            #pragma unroll 8
            for (int k = 0; k < DDIM / 4; k++) {
                float4 va = fr[k], vb = fj[k];
                s += va.x * vb.x + va.y * vb.y + va.z * vb.z + va.w * vb.w;
            }
            topk_ins(s * g_invn[j], j, bv, bi);
        }
    }

    // 10 rounds of warp argmax ((v desc, idx asc) comparator) with pop
    #pragma unroll 1
    for (int r = 0; r < KN; r++) {
        float mv = bv[0]; int mi = bi[0];
        #pragma unroll
        for (int off = 16; off; off >>= 1) {
            float ov = __shfl_xor_sync(0xffffffffu, mv, off);
            int   oi = __shfl_xor_sync(0xffffffffu, mi, off);
            if (ov > mv || (ov == mv && oi < mi)) { mv = ov; mi = oi; }
        }
        if (mi == bi[0]) {
            #pragma unroll
            for (int t = 0; t < KN - 1; t++) { bv[t] = bv[t + 1]; bi[t] = bi[t + 1]; }
            bv[KN - 1] = NEG_INF; bi[KN - 1] = 0x7fffffff;
        }
        if (lane == 0) {
            g_topk[row * KN + r] = mi;
            atomicAdd(&g_dv[mi], 1);
        }
    }
}

// ---------------- kernel 4: scatter 10x10 outer products (inv_dv fused) ----------------
__global__ __launch_bounds__(128) void k_scatter(float* __restrict__ out) {
    __shared__ int   sidx[KN];
    __shared__ float sw[KN];
    int e = blockIdx.x;
    int t = threadIdx.x;
    if (t < KN) {
        int a = g_topk[e * KN + t];
        sidx[t] = a;
        int d = g_dv[a];
        sw[t] = d > 0 ? 1.0f / sqrtf((float)d) : 0.0f;
    }
    __syncthreads();
    if (t < KN * KN) {
        int a = sidx[t / KN];
        int b = sidx[t % KN];
        float val = (0.1f * sw[t / KN]) * sw[t % KN];
        atomicAdd(&out[(size_t)a * NROWS + b], val);
    }
}

// ---------------- launch ----------------
extern "C" void kernel_launch(void* const* d_in, const int* in_sizes, int n_in,
                              void* d_out, int out_size) {
    const float* feats = (const float*)d_in[0];
    float* out = (float*)d_out;

    k_prep<<<(NROWS * 32) / 256, 256>>>(feats);

    cudaFuncSetAttribute(k_gemm, cudaFuncAttributeMaxDynamicSharedMemorySize, GEMM_SMEM);
    k_gemm<<<NTRI, 256, GEMM_SMEM>>>((float4*)out);

    k_topk<<<NROWS / 8, 256>>>(feats);
    k_scatter<<<NROWS, 128>>>(out);
}